// round 14
// baseline (speedup 1.0000x reference)
#include <cuda_runtime.h>
#include <cuda_fp16.h>
#include <cstddef>
#include <cstdint>

#define NB  8
#define NS  1024
#define NH  12
#define ND  768
#define NDH 64

// log2(e)/8 : folded into Q so QK^T scores land in log2 domain
#define QSCALE 0.18033688011112042f

// ---------------- device scratch (no allocations allowed) ----------------
__device__ __half g_xh[(size_t)NB * NS * ND];          // x as fp16 [m][d]
__device__ __half g_wt[3][(size_t)ND * ND];            // W^T per sel: [(h,e)][d]
__device__ __half g_wo_h[(size_t)ND * ND];             // Wo as fp16 [n][k]
__device__ __half g_q[(size_t)NB * NH * NS * NDH];     // pre-scaled by QSCALE
__device__ __half g_k[(size_t)NB * NH * NS * NDH];
__device__ __half g_v[(size_t)NB * NH * NS * NDH];
__device__ __half g_ctx[(size_t)NB * NS * ND];         // [m][(h,e)]
__device__ float  g_probs_fb[(size_t)NB * NH * NS * NS];

// ---------------- helpers ----------------
__device__ __forceinline__ void cp16(__half* dst, const __half* src) {
    unsigned d = (unsigned)__cvta_generic_to_shared(dst);
    asm volatile("cp.async.cg.shared.global [%0], [%1], 16;" :: "r"(d), "l"(src));
}
__device__ __forceinline__ void cp_commit() {
    asm volatile("cp.async.commit_group;" ::: "memory");
}
__device__ __forceinline__ void cp_wait0() {
    asm volatile("cp.async.wait_group 0;" ::: "memory");
}
__device__ __forceinline__ void ldsm4(unsigned r[4], unsigned addr) {
    asm volatile("ldmatrix.sync.aligned.m8n8.x4.shared.b16 {%0,%1,%2,%3}, [%4];"
                 : "=r"(r[0]), "=r"(r[1]), "=r"(r[2]), "=r"(r[3]) : "r"(addr));
}
__device__ __forceinline__ void ldsm4t(unsigned r[4], unsigned addr) {
    asm volatile("ldmatrix.sync.aligned.m8n8.x4.trans.shared.b16 {%0,%1,%2,%3}, [%4];"
                 : "=r"(r[0]), "=r"(r[1]), "=r"(r[2]), "=r"(r[3]) : "r"(addr));
}
__device__ __forceinline__ void mma16(float c[4], const unsigned a[4],
                                      unsigned b0, unsigned b1) {
    asm volatile(
        "mma.sync.aligned.m16n8k16.row.col.f32.f16.f16.f32 "
        "{%0,%1,%2,%3},{%4,%5,%6,%7},{%8,%9},{%0,%1,%2,%3};"
        : "+f"(c[0]), "+f"(c[1]), "+f"(c[2]), "+f"(c[3])
        : "r"(a[0]), "r"(a[1]), "r"(a[2]), "r"(a[3]), "r"(b0), "r"(b1));
}
__device__ __forceinline__ unsigned pack_h2(float lo, float hi) {
    __half2 h = __floats2half2_rn(lo, hi);
    return *reinterpret_cast<unsigned*>(&h);
}
__device__ __forceinline__ unsigned ex2h2(unsigned x) {
    unsigned y;
    asm("ex2.approx.f16x2 %0, %1;" : "=r"(y) : "r"(x));
    return y;
}
__device__ __forceinline__ float ex2f(float x) {
    float y;
    asm("ex2.approx.f32 %0, %1;" : "=f"(y) : "f"(x));
    return y;
}
__device__ __forceinline__ unsigned hadd2(unsigned a, unsigned b) {
    unsigned d;
    asm("add.f16x2 %0, %1, %2;" : "=r"(d) : "r"(a), "r"(b));
    return d;
}
__device__ __forceinline__ float2 h2_to_f2(unsigned u) {
    __half2 h = *reinterpret_cast<__half2*>(&u);
    return __half22float2(h);
}
__device__ __forceinline__ int a_off(int lane, int LD) {
    return ((lane & 7) + ((lane >> 3) & 1) * 8) * LD + (lane >> 4) * 8;
}
__device__ __forceinline__ int b_off(int lane, int LD) {
    return ((lane & 7) + (lane >> 4) * 8) * LD + ((lane >> 3) & 1) * 8;
}

// ---------------------------------------------------------------------------
// Kernel 0a: elementwise fp16 conversion for x and Wo (both coalesced).
// ---------------------------------------------------------------------------
__global__ void prep_convert(const float* __restrict__ x,
                             const float* __restrict__ Wo)
{
    const int i = blockIdx.x * blockDim.x + threadIdx.x;
    if (i < (NB * NS * ND) / 4) {
        float4 v = ((const float4*)x)[i];
        ((__half2*)g_xh)[i * 2]     = __floats2half2_rn(v.x, v.y);
        ((__half2*)g_xh)[i * 2 + 1] = __floats2half2_rn(v.z, v.w);
    }
    if (i < (ND * ND) / 4) {
        float4 v = ((const float4*)Wo)[i];
        ((__half2*)g_wo_h)[i * 2]     = __floats2half2_rn(v.x, v.y);
        ((__half2*)g_wo_h)[i * 2 + 1] = __floats2half2_rn(v.z, v.w);
    }
}

// ---------------------------------------------------------------------------
// Kernel 0b: coalesced W transpose via smem tile.
// ---------------------------------------------------------------------------
__global__ __launch_bounds__(256) void prep_wt(const float* __restrict__ Wq,
                                               const float* __restrict__ Wk,
                                               const float* __restrict__ Wv)
{
    __shared__ __half smh[64 * 72];
    const int d0  = blockIdx.x * 64;
    const int h   = blockIdx.y;
    const int sel = blockIdx.z;
    const float* W = (sel == 0) ? Wq : (sel == 1) ? Wk : Wv;
    const int tid = threadIdx.x;

    #pragma unroll
    for (int p = 0; p < 4; p++) {
        int i = tid + p * 256;
        int row = i >> 4, c4 = (i & 15) * 4;
        float4 v = *(const float4*)&W[((size_t)h * ND + d0 + row) * NDH + c4];
        smh[(c4 + 0) * 72 + row] = __float2half_rn(v.x);
        smh[(c4 + 1) * 72 + row] = __float2half_rn(v.y);
        smh[(c4 + 2) * 72 + row] = __float2half_rn(v.z);
        smh[(c4 + 3) * 72 + row] = __float2half_rn(v.w);
    }
    __syncthreads();

    #pragma unroll
    for (int p = 0; p < 2; p++) {
        int i = tid + p * 256;
        int e = i >> 3, c8 = (i & 7) * 8;
        *(uint4*)&g_wt[sel][((size_t)h * 64 + e) * ND + d0 + c8] =
            *(uint4*)&smh[e * 72 + c8];
    }
}

// ---------------------------------------------------------------------------
// Kernel 1: QKV projection fp16 mma, 64x128 CTA tile (anti-tail), warps 2x4,
// warp tile 32x32, cp.async double-buffered. Q output pre-scaled by QSCALE.
// ---------------------------------------------------------------------------
__global__ __launch_bounds__(256, 2) void qkv_mma(
    const float* __restrict__ bq, const float* __restrict__ bk,
    const float* __restrict__ bv)
{
    extern __shared__ __half smh[];
    __half* As = smh;                 // 2 x 64 x 72
    __half* Bs = smh + 2 * 64 * 72;   // 2 x 128 x 72

    const int sel = blockIdx.z;
    const __half* wt = g_wt[sel];
    const float* bias = (sel == 0) ? bq : (sel == 1) ? bk : bv;
    __half* out = (sel == 0) ? g_q : (sel == 1) ? g_k : g_v;
    const float osc = (sel == 0) ? QSCALE : 1.0f;

    const int tid = threadIdx.x, lane = tid & 31, warp = tid >> 5;
    const int gid = lane >> 2, tig = lane & 3;
    const int wm = warp >> 2, wn = warp & 3;
    const int m0 = blockIdx.x * 64, n0 = blockIdx.y * 128;

    const unsigned As_sh = (unsigned)__cvta_generic_to_shared(As);
    const unsigned Bs_sh = (unsigned)__cvta_generic_to_shared(Bs);
    const int aoff = a_off(lane, 72), boff = b_off(lane, 72);

    auto issue = [&](int c) {
        __half* A = As + (c & 1) * 64 * 72;
        __half* B = Bs + (c & 1) * 128 * 72;
        const int k0 = c * 64;
        #pragma unroll
        for (int p = 0; p < 2; p++) {
            int i = tid + p * 256;
            int row = i >> 3, c8 = (i & 7) * 8;
            cp16(&A[row * 72 + c8], &g_xh[(size_t)(m0 + row) * ND + k0 + c8]);
        }
        #pragma unroll
        for (int p = 0; p < 4; p++) {
            int i = tid + p * 256;
            int row = i >> 3, c8 = (i & 7) * 8;
            cp16(&B[row * 72 + c8], &wt[(size_t)(n0 + row) * ND + k0 + c8]);
        }
        cp_commit();
    };

    float acc[2][4][4] = {};

    issue(0);
    for (int c = 0; c < 12; c++) {
        cp_wait0();
        __syncthreads();
        if (c + 1 < 12) issue(c + 1);

        const unsigned Ab = As_sh + (c & 1) * 64 * 72 * 2;
        const unsigned Bb = Bs_sh + (c & 1) * 128 * 72 * 2;

        #pragma unroll
        for (int ks = 0; ks < 4; ks++) {
            const int Kb = ks * 16;
            unsigned a[2][4], b[4][2];
            #pragma unroll
            for (int i = 0; i < 2; i++)
                ldsm4(a[i], Ab + ((wm * 32 + i * 16) * 72 + Kb + aoff) * 2);
            #pragma unroll
            for (int jj = 0; jj < 2; jj++) {
                unsigned t[4];
                ldsm4(t, Bb + ((wn * 32 + jj * 16) * 72 + Kb + boff) * 2);
                b[jj * 2][0] = t[0]; b[jj * 2][1] = t[1];
                b[jj * 2 + 1][0] = t[2]; b[jj * 2 + 1][1] = t[3];
            }
            #pragma unroll
            for (int i = 0; i < 2; i++)
                #pragma unroll
                for (int j = 0; j < 4; j++)
                    mma16(acc[i][j], a[i], b[j][0], b[j][1]);
        }
    }

    #pragma unroll
    for (int i = 0; i < 2; i++) {
        #pragma unroll
        for (int j = 0; j < 4; j++) {
            int col_g = n0 + wn * 32 + (j >> 1) * 16 + (j & 1) * 8 + 2 * tig;
            int hh = col_g >> 6, e = col_g & 63;
            float b0 = bias[col_g], b1 = bias[col_g + 1];
            int m = m0 + wm * 32 + i * 16 + gid;
            int bb = m >> 10, s = m & 1023;
            *(__half2*)&out[(((size_t)bb * NH + hh) * NS + s) * NDH + e] =
                __floats2half2_rn((acc[i][j][0] + b0) * osc, (acc[i][j][1] + b1) * osc);
            m += 8; bb = m >> 10; s = m & 1023;
            *(__half2*)&out[(((size_t)bb * NH + hh) * NS + s) * NDH + e] =
                __floats2half2_rn((acc[i][j][2] + b0) * osc, (acc[i][j][3] + b1) * osc);
        }
    }
}

// ---------------------------------------------------------------------------
// Kernel 2: fused attention (round-10 proven version, unchanged).
// ---------------------------------------------------------------------------
__global__ __launch_bounds__(256, 2) void attn_fused(float* __restrict__ probs)
{
    extern __shared__ __half smh[];
    __half* Qs = smh;                  // 64 x 72
    __half* Kb = Qs + 64 * 72;         // 2 x 64 x 72
    __half* Vb = Kb + 2 * 64 * 72;     // 2 x 64 x 72
    float* red  = (float*)(Vb + 2 * 64 * 72);  // 64 x 68
    float* ssum = red + 64 * 68;               // 2 x 64
    float* sinv = ssum + 128;                  // 64

    const int bh = blockIdx.y;
    const int s0 = blockIdx.x * 64;
    const __half* qg = g_q + (size_t)bh * NS * NDH;
    const __half* kg = g_k + (size_t)bh * NS * NDH;
    const __half* vg = g_v + (size_t)bh * NS * NDH;

    const int tid = threadIdx.x, lane = tid & 31, warp = tid >> 5;
    const int gid = lane >> 2, tig = lane & 3;
    const int wm = warp >> 1, wn = warp & 1;   // 4 x 2

    const unsigned Q_sh = (unsigned)__cvta_generic_to_shared(Qs);
    const unsigned K_sh = (unsigned)__cvta_generic_to_shared(Kb);
    const unsigned V_sh = (unsigned)__cvta_generic_to_shared(Vb);
    const int aoff = a_off(lane, 72), boff = b_off(lane, 72);

    auto issue_k = [&](int kt) {
        __half* K = Kb + (kt & 1) * 64 * 72;
        const __half* src = kg + (size_t)kt * 64 * NDH;
        #pragma unroll
        for (int p = 0; p < 2; p++) {
            int i = tid + p * 256;
            int row = i >> 3, c8 = (i & 7) * 8;
            cp16(&K[row * 72 + c8], &src[row * 64 + c8]);
        }
    };
    auto issue_v = [&](int kt) {
        __half* V = Vb + (kt & 1) * 64 * 72;
        const __half* src = vg + (size_t)kt * 64 * NDH;
        #pragma unroll
        for (int p = 0; p < 2; p++) {
            int i = tid + p * 256;
            int row = i >> 3, c8 = (i & 7) * 8;
            cp16(&V[row * 72 + c8], &src[row * 64 + c8]);
        }
    };

    #pragma unroll
    for (int p = 0; p < 2; p++) {
        int i = tid + p * 256;
        int row = i >> 3, c8 = (i & 7) * 8;
        cp16(&Qs[row * 72 + c8], &qg[(size_t)(s0 + row) * 64 + c8]);
    }
    issue_k(0); issue_v(0);
    cp_commit();

    unsigned aq[4][4];
    float ccv[8][4] = {};
    float srow[2] = {};

    for (int kt = 0; kt < 16; kt++) {
        cp_wait0();
        __syncthreads();
        if (kt + 1 < 16) { issue_k(kt + 1); issue_v(kt + 1); cp_commit(); }

        if (kt == 0) {
            #pragma unroll
            for (int e = 0; e < 4; e++)
                ldsm4(aq[e], Q_sh + ((wm * 16) * 72 + e * 16 + aoff) * 2);
        }

        const unsigned Kbuf = K_sh + (kt & 1) * 64 * 72 * 2;
        const unsigned Vbuf = V_sh + (kt & 1) * 64 * 72 * 2;

        float cc[4][4] = {};
        #pragma unroll
        for (int e = 0; e < 4; e++) {
            #pragma unroll
            for (int nt = 0; nt < 2; nt++) {
                unsigned t[4];
                ldsm4(t, Kbuf + ((wn * 32 + nt * 16) * 72 + e * 16 + boff) * 2);
                mma16(cc[nt * 2 + 0], aq[e], t[0], t[1]);
                mma16(cc[nt * 2 + 1], aq[e], t[2], t[3]);
            }
        }

        unsigned pa[2][4];
        #pragma unroll
        for (int ks = 0; ks < 2; ks++) {
            pa[ks][0] = ex2h2(pack_h2(cc[ks * 2][0],     cc[ks * 2][1]));
            pa[ks][1] = ex2h2(pack_h2(cc[ks * 2][2],     cc[ks * 2][3]));
            pa[ks][2] = ex2h2(pack_h2(cc[ks * 2 + 1][0], cc[ks * 2 + 1][1]));
            pa[ks][3] = ex2h2(pack_h2(cc[ks * 2 + 1][2], cc[ks * 2 + 1][3]));
        }
        {
            unsigned slo = hadd2(hadd2(pa[0][0], pa[0][2]), hadd2(pa[1][0], pa[1][2]));
            unsigned shi = hadd2(hadd2(pa[0][1], pa[0][3]), hadd2(pa[1][1], pa[1][3]));
            float2 f0 = h2_to_f2(slo); srow[0] += f0.x + f0.y;
            float2 f1 = h2_to_f2(shi); srow[1] += f1.x + f1.y;
        }

        #pragma unroll
        for (int ks = 0; ks < 2; ks++) {
            #pragma unroll
            for (int e0 = 0; e0 < 4; e0++) {
                unsigned bt[4];
                ldsm4t(bt, Vbuf + ((wn * 32 + ks * 16) * 72 + e0 * 16 + aoff) * 2);
                mma16(ccv[e0 * 2 + 0], pa[ks], bt[0], bt[1]);
                mma16(ccv[e0 * 2 + 1], pa[ks], bt[2], bt[3]);
            }
        }
    }

    srow[0] += __shfl_xor_sync(0xFFFFFFFFu, srow[0], 1);
    srow[0] += __shfl_xor_sync(0xFFFFFFFFu, srow[0], 2);
    srow[1] += __shfl_xor_sync(0xFFFFFFFFu, srow[1], 1);
    srow[1] += __shfl_xor_sync(0xFFFFFFFFu, srow[1], 2);
    if (tig == 0) {
        ssum[wn * 64 + wm * 16 + gid]     = srow[0];
        ssum[wn * 64 + wm * 16 + gid + 8] = srow[1];
    }
    if (wn == 1) {
        #pragma unroll
        for (int f = 0; f < 8; f++) {
            int col = f * 8 + 2 * tig;
            *(float2*)&red[(wm * 16 + gid) * 68 + col]     = *(float2*)&ccv[f][0];
            *(float2*)&red[(wm * 16 + gid + 8) * 68 + col] = *(float2*)&ccv[f][2];
        }
    }
    issue_k(0); cp_commit();
    __syncthreads();
    if (tid < 64)
        sinv[tid] = 1.0f / (ssum[tid] + ssum[64 + tid]);
    __syncthreads();

    if (wn == 0) {
        const int b = bh / NH, h = bh % NH;
        const float ilo = sinv[wm * 16 + gid];
        const float ihi = sinv[wm * 16 + gid + 8];
        #pragma unroll
        for (int f = 0; f < 8; f++) {
            int col = f * 8 + 2 * tig;
            float2 r0 = *(float2*)&red[(wm * 16 + gid) * 68 + col];
            float2 r1 = *(float2*)&red[(wm * 16 + gid + 8) * 68 + col];
            int sr = s0 + wm * 16 + gid;
            *(__half2*)&g_ctx[((size_t)b * NS + sr) * ND + h * NDH + col] =
                __floats2half2_rn((ccv[f][0] + r0.x) * ilo, (ccv[f][1] + r0.y) * ilo);
            *(__half2*)&g_ctx[((size_t)b * NS + sr + 8) * ND + h * NDH + col] =
                __floats2half2_rn((ccv[f][2] + r1.x) * ihi, (ccv[f][3] + r1.y) * ihi);
        }
    }

    const float inv_lo = sinv[wm * 16 + gid];
    const float inv_hi = sinv[wm * 16 + gid + 8];
    float* prow_lo = probs + ((size_t)bh * NS + s0 + wm * 16 + gid) * NS;
    float* prow_hi = prow_lo + (size_t)8 * NS;

    for (int kt = 0; kt < 16; kt++) {
        cp_wait0();
        __syncthreads();
        if (kt + 1 < 16) { issue_k(kt + 1); cp_commit(); }

        const unsigned Kbuf = K_sh + (kt & 1) * 64 * 72 * 2;
        float cc[4][4] = {};
        #pragma unroll
        for (int e = 0; e < 4; e++) {
            #pragma unroll
            for (int nt = 0; nt < 2; nt++) {
                unsigned t[4];
                ldsm4(t, Kbuf + ((wn * 32 + nt * 16) * 72 + e * 16 + boff) * 2);
                mma16(cc[nt * 2 + 0], aq[e], t[0], t[1]);
                mma16(cc[nt * 2 + 1], aq[e], t[2], t[3]);
            }
        }

        #pragma unroll
        for (int jj = 0; jj < 4; jj++) {
            const int col = kt * 64 + wn * 32 + (jj >> 1) * 16 + (jj & 1) * 8 + 2 * tig;
            float2 w0, w1;
            w0.x = ex2f(cc[jj][0]) * inv_lo;
            w0.y = ex2f(cc[jj][1]) * inv_lo;
            w1.x = ex2f(cc[jj][2]) * inv_hi;
            w1.y = ex2f(cc[jj][3]) * inv_hi;
            *(float2*)&prow_lo[col] = w0;
            *(float2*)&prow_hi[col] = w1;
        }
    }
}

// ---------------------------------------------------------------------------
// Kernel 3: out = ctx @ Wo^T + bo, fp16 mma, fp32 out. 64x128 CTA tile
// (anti-tail: 768 CTAs = 2.6 waves vs 1.3), warps 2x4, warp tile 32x32.
// ---------------------------------------------------------------------------
__global__ __launch_bounds__(256, 2) void oproj_mma(
    const float* __restrict__ bo, float* __restrict__ out)
{
    extern __shared__ __half smh[];
    __half* As = smh;                 // 2 x 64 x 72
    __half* Bs = smh + 2 * 64 * 72;   // 2 x 128 x 72

    const int tid = threadIdx.x, lane = tid & 31, warp = tid >> 5;
    const int gid = lane >> 2, tig = lane & 3;
    const int wm = warp >> 2, wn = warp & 3;
    const int m0 = blockIdx.x * 64, n0 = blockIdx.y * 128;

    const unsigned As_sh = (unsigned)__cvta_generic_to_shared(As);
    const unsigned Bs_sh = (unsigned)__cvta_generic_to_shared(Bs);
    const int aoff = a_off(lane, 72), boff = b_off(lane, 72);

    auto issue = [&](int c) {
        __half* A = As + (c & 1) * 64 * 72;
        __half* B = Bs + (c & 1) * 128 * 72;
        const int k0 = c * 64;
        #pragma unroll
        for (int p = 0; p < 2; p++) {
            int i = tid + p * 256;
            int row = i >> 3, c8 = (i & 7) * 8;
            cp16(&A[row * 72 + c8], &g_ctx[(size_t)(m0 + row) * ND + k0 + c8]);
        }
        #pragma unroll
        for (int p = 0; p < 4; p++) {
            int i = tid + p * 256;
            int row = i >> 3, c8 = (i & 7) * 8;
            cp16(&B[row * 72 + c8], &g_wo_h[(size_t)(n0 + row) * ND + k0 + c8]);
        }
        cp_commit();
    };

    float acc[2][4][4] = {};

    issue(0);
    for (int c = 0; c < 12; c++) {
        cp_wait0();
        __syncthreads();
        if (c + 1 < 12) issue(c + 1);

        const unsigned Ab = As_sh + (c & 1) * 64 * 72 * 2;
        const unsigned Bb = Bs_sh + (c & 1) * 128 * 72 * 2;

        #pragma unroll
        for (int ks = 0; ks < 4; ks++) {
            const int Kb = ks * 16;
            unsigned a[2][4], b[4][2];
            #pragma unroll
            for (int i = 0; i < 2; i++)
                ldsm4(a[i], Ab + ((wm * 32 + i * 16) * 72 + Kb + aoff) * 2);
            #pragma unroll
            for (int jj = 0; jj < 2; jj++) {
                unsigned t[4];
                ldsm4(t, Bb + ((wn * 32 + jj * 16) * 72 + Kb + boff) * 2);
                b[jj * 2][0] = t[0]; b[jj * 2][1] = t[1];
                b[jj * 2 + 1][0] = t[2]; b[jj * 2 + 1][1] = t[3];
            }
            #pragma unroll
            for (int i = 0; i < 2; i++)
                #pragma unroll
                for (int j = 0; j < 4; j++)
                    mma16(acc[i][j], a[i], b[j][0], b[j][1]);
        }
    }

    #pragma unroll
    for (int i = 0; i < 2; i++) {
        #pragma unroll
        for (int j = 0; j < 4; j++) {
            int col = n0 + wn * 32 + (j >> 1) * 16 + (j & 1) * 8 + 2 * tig;
            float b0 = bo[col], b1 = bo[col + 1];
            int m = m0 + wm * 32 + i * 16 + gid;
            float2 v;
            v.x = acc[i][j][0] + b0; v.y = acc[i][j][1] + b1;
            *(float2*)&out[(size_t)m * ND + col] = v;
            v.x = acc[i][j][2] + b0; v.y = acc[i][j][3] + b1;
            *(float2*)&out[(size_t)(m + 8) * ND + col] = v;
        }
    }
}

// ---------------------------------------------------------------------------
extern "C" void kernel_launch(void* const* d_in, const int* in_sizes, int n_in,
                              void* d_out, int out_size)
{
    const float* x  = (const float*)d_in[0];
    const float* Wq = (const float*)d_in[1];
    const float* bq = (const float*)d_in[2];
    const float* Wk = (const float*)d_in[3];
    const float* bk = (const float*)d_in[4];
    const float* Wv = (const float*)d_in[5];
    const float* bv = (const float*)d_in[6];
    const float* Wo = (const float*)d_in[7];
    const float* bo = (const float*)d_in[8];

    float* out = (float*)d_out;

    const size_t BSD  = (size_t)NB * NS * ND;
    const size_t BHSS = (size_t)NB * NH * NS * NS;

    float* probs;
    if ((size_t)out_size >= BSD + BHSS) {
        probs = out + BSD;
    } else {
        cudaGetSymbolAddress((void**)&probs, g_probs_fb);
    }

    const int gemm_smem = (2 * 64 * 72 + 2 * 128 * 72) * 2;            // 55,296 B
    const int attn_smem = (64 * 72 * 5) * 2 + (64 * 68 + 128 + 64) * 4; // 64,256 B
    cudaFuncSetAttribute(qkv_mma,    cudaFuncAttributeMaxDynamicSharedMemorySize, gemm_smem);
    cudaFuncSetAttribute(attn_fused, cudaFuncAttributeMaxDynamicSharedMemorySize, attn_smem);
    cudaFuncSetAttribute(oproj_mma,  cudaFuncAttributeMaxDynamicSharedMemorySize, gemm_smem);

    prep_convert<<<6144, 256>>>(x, Wo);
    prep_wt     <<<dim3(12, 12, 3), 256>>>(Wq, Wk, Wv);
    qkv_mma     <<<dim3(128, 6, 3), 256, gemm_smem>>>(bq, bk, bv);
    attn_fused  <<<dim3(16, 96), 256, attn_smem>>>(probs);
    oproj_mma   <<<dim3(128, 6), 256, gemm_smem>>>(bo, out);
}

// round 16
// speedup vs baseline: 1.0752x; 1.0752x over previous
#include <cuda_runtime.h>
#include <cuda_fp16.h>
#include <cstddef>
#include <cstdint>

#define NB  8
#define NS  1024
#define NH  12
#define ND  768
#define NDH 64

// log2(e)/8 : folded into Q so QK^T scores land in log2 domain
#define QSCALE 0.18033688011112042f

// ---------------- device scratch (no allocations allowed) ----------------
__device__ __half g_xh[(size_t)NB * NS * ND];          // x as fp16 [m][d]
__device__ __half g_wt[3][(size_t)ND * ND];            // W^T per sel: [(h,e)][d]
__device__ __half g_wo_h[(size_t)ND * ND];             // Wo as fp16 [n][k]
__device__ __half g_q[(size_t)NB * NH * NS * NDH];     // pre-scaled by QSCALE
__device__ __half g_k[(size_t)NB * NH * NS * NDH];
__device__ __half g_v[(size_t)NB * NH * NS * NDH];
__device__ __half g_ctx[(size_t)NB * NS * ND];         // [m][(h,e)]
__device__ float  g_probs_fb[(size_t)NB * NH * NS * NS];

// ---------------- helpers ----------------
__device__ __forceinline__ void cp16(__half* dst, const __half* src) {
    unsigned d = (unsigned)__cvta_generic_to_shared(dst);
    asm volatile("cp.async.cg.shared.global [%0], [%1], 16;" :: "r"(d), "l"(src));
}
__device__ __forceinline__ void cp_commit() {
    asm volatile("cp.async.commit_group;" ::: "memory");
}
__device__ __forceinline__ void cp_wait0() {
    asm volatile("cp.async.wait_group 0;" ::: "memory");
}
__device__ __forceinline__ void ldsm4(unsigned r[4], unsigned addr) {
    asm volatile("ldmatrix.sync.aligned.m8n8.x4.shared.b16 {%0,%1,%2,%3}, [%4];"
                 : "=r"(r[0]), "=r"(r[1]), "=r"(r[2]), "=r"(r[3]) : "r"(addr));
}
__device__ __forceinline__ void ldsm4t(unsigned r[4], unsigned addr) {
    asm volatile("ldmatrix.sync.aligned.m8n8.x4.trans.shared.b16 {%0,%1,%2,%3}, [%4];"
                 : "=r"(r[0]), "=r"(r[1]), "=r"(r[2]), "=r"(r[3]) : "r"(addr));
}
__device__ __forceinline__ void mma16(float c[4], const unsigned a[4],
                                      unsigned b0, unsigned b1) {
    asm volatile(
        "mma.sync.aligned.m16n8k16.row.col.f32.f16.f16.f32 "
        "{%0,%1,%2,%3},{%4,%5,%6,%7},{%8,%9},{%0,%1,%2,%3};"
        : "+f"(c[0]), "+f"(c[1]), "+f"(c[2]), "+f"(c[3])
        : "r"(a[0]), "r"(a[1]), "r"(a[2]), "r"(a[3]), "r"(b0), "r"(b1));
}
__device__ __forceinline__ unsigned pack_h2(float lo, float hi) {
    __half2 h = __floats2half2_rn(lo, hi);
    return *reinterpret_cast<unsigned*>(&h);
}
__device__ __forceinline__ unsigned ex2h2(unsigned x) {
    unsigned y;
    asm("ex2.approx.f16x2 %0, %1;" : "=r"(y) : "r"(x));
    return y;
}
__device__ __forceinline__ float ex2f(float x) {
    float y;
    asm("ex2.approx.f32 %0, %1;" : "=f"(y) : "f"(x));
    return y;
}
__device__ __forceinline__ unsigned hadd2(unsigned a, unsigned b) {
    unsigned d;
    asm("add.f16x2 %0, %1, %2;" : "=r"(d) : "r"(a), "r"(b));
    return d;
}
__device__ __forceinline__ float2 h2_to_f2(unsigned u) {
    __half2 h = *reinterpret_cast<__half2*>(&u);
    return __half22float2(h);
}
__device__ __forceinline__ int a_off(int lane, int LD) {
    return ((lane & 7) + ((lane >> 3) & 1) * 8) * LD + (lane >> 4) * 8;
}
__device__ __forceinline__ int b_off(int lane, int LD) {
    return ((lane & 7) + (lane >> 4) * 8) * LD + ((lane >> 3) & 1) * 8;
}

// ---------------------------------------------------------------------------
// Kernel 0: merged prep.
// Blocks [0, 6144): fp16 convert — i is a float4 index; x needs
//   (8*1024*768)/4 = 1,572,864 float4s = 6144 blocks x 256 threads.
// Blocks [6144, 6576): coalesced W transpose (12 d-tiles x 12 heads x 3 sels).
// ---------------------------------------------------------------------------
#define PREP_CVT_BLOCKS 6144
#define PREP_WT_BLOCKS  432

__global__ __launch_bounds__(256) void prep_all(
    const float* __restrict__ x,  const float* __restrict__ Wo,
    const float* __restrict__ Wq, const float* __restrict__ Wk,
    const float* __restrict__ Wv)
{
    __shared__ __half smh[64 * 72];
    const int tid = threadIdx.x;

    if (blockIdx.x < PREP_CVT_BLOCKS) {
        const int i = blockIdx.x * 256 + tid;       // float4 index
        if (i < (NB * NS * ND) / 4) {
            float4 v = ((const float4*)x)[i];
            ((__half2*)g_xh)[i * 2]     = __floats2half2_rn(v.x, v.y);
            ((__half2*)g_xh)[i * 2 + 1] = __floats2half2_rn(v.z, v.w);
        }
        if (i < (ND * ND) / 4) {
            float4 v = ((const float4*)Wo)[i];
            ((__half2*)g_wo_h)[i * 2]     = __floats2half2_rn(v.x, v.y);
            ((__half2*)g_wo_h)[i * 2 + 1] = __floats2half2_rn(v.z, v.w);
        }
        return;
    }

    // transpose part
    const int bi  = blockIdx.x - PREP_CVT_BLOCKS;
    const int d0  = (bi % 12) * 64;
    const int h   = (bi / 12) % 12;
    const int sel = bi / 144;
    const float* W = (sel == 0) ? Wq : (sel == 1) ? Wk : Wv;

    #pragma unroll
    for (int p = 0; p < 4; p++) {
        int i = tid + p * 256;
        int row = i >> 4, c4 = (i & 15) * 4;
        float4 v = *(const float4*)&W[((size_t)h * ND + d0 + row) * NDH + c4];
        smh[(c4 + 0) * 72 + row] = __float2half_rn(v.x);
        smh[(c4 + 1) * 72 + row] = __float2half_rn(v.y);
        smh[(c4 + 2) * 72 + row] = __float2half_rn(v.z);
        smh[(c4 + 3) * 72 + row] = __float2half_rn(v.w);
    }
    __syncthreads();

    #pragma unroll
    for (int p = 0; p < 2; p++) {
        int i = tid + p * 256;
        int e = i >> 3, c8 = (i & 7) * 8;
        *(uint4*)&g_wt[sel][((size_t)h * 64 + e) * ND + d0 + c8] =
            *(uint4*)&smh[e * 72 + c8];
    }
}

// ---------------------------------------------------------------------------
// Kernel 1: QKV projection fp16 mma (round-10 proven: 128x128 CTA tile,
// warps 2x4, warp tile 64x32, cp.async double-buffered). Q pre-scaled.
// ---------------------------------------------------------------------------
__global__ __launch_bounds__(256, 2) void qkv_mma(
    const float* __restrict__ bq, const float* __restrict__ bk,
    const float* __restrict__ bv)
{
    extern __shared__ __half smh[];
    __half* As = smh;                 // 2 x 128 x 72
    __half* Bs = smh + 2 * 128 * 72;  // 2 x 128 x 72

    const int sel = blockIdx.z;
    const __half* wt = g_wt[sel];
    const float* bias = (sel == 0) ? bq : (sel == 1) ? bk : bv;
    __half* out = (sel == 0) ? g_q : (sel == 1) ? g_k : g_v;
    const float osc = (sel == 0) ? QSCALE : 1.0f;

    const int tid = threadIdx.x, lane = tid & 31, warp = tid >> 5;
    const int gid = lane >> 2, tig = lane & 3;
    const int wm = warp >> 2, wn = warp & 3;
    const int m0 = blockIdx.x * 128, n0 = blockIdx.y * 128;

    const unsigned As_sh = (unsigned)__cvta_generic_to_shared(As);
    const unsigned Bs_sh = (unsigned)__cvta_generic_to_shared(Bs);
    const int aoff = a_off(lane, 72), boff = b_off(lane, 72);

    auto issue = [&](int c) {
        __half* A = As + (c & 1) * 128 * 72;
        __half* B = Bs + (c & 1) * 128 * 72;
        const int k0 = c * 64;
        #pragma unroll
        for (int p = 0; p < 4; p++) {
            int i = tid + p * 256;
            int row = i >> 3, c8 = (i & 7) * 8;
            cp16(&A[row * 72 + c8], &g_xh[(size_t)(m0 + row) * ND + k0 + c8]);
        }
        #pragma unroll
        for (int p = 0; p < 4; p++) {
            int i = tid + p * 256;
            int row = i >> 3, c8 = (i & 7) * 8;
            cp16(&B[row * 72 + c8], &wt[(size_t)(n0 + row) * ND + k0 + c8]);
        }
        cp_commit();
    };

    float acc[4][4][4] = {};

    issue(0);
    for (int c = 0; c < 12; c++) {
        cp_wait0();
        __syncthreads();
        if (c + 1 < 12) issue(c + 1);

        const unsigned Ab = As_sh + (c & 1) * 128 * 72 * 2;
        const unsigned Bb = Bs_sh + (c & 1) * 128 * 72 * 2;

        #pragma unroll
        for (int ks = 0; ks < 4; ks++) {
            const int Kb = ks * 16;
            unsigned a[4][4], b[4][2];
            #pragma unroll
            for (int i = 0; i < 4; i++)
                ldsm4(a[i], Ab + ((wm * 64 + i * 16) * 72 + Kb + aoff) * 2);
            #pragma unroll
            for (int jj = 0; jj < 2; jj++) {
                unsigned t[4];
                ldsm4(t, Bb + ((wn * 32 + jj * 16) * 72 + Kb + boff) * 2);
                b[jj * 2][0] = t[0]; b[jj * 2][1] = t[1];
                b[jj * 2 + 1][0] = t[2]; b[jj * 2 + 1][1] = t[3];
            }
            #pragma unroll
            for (int i = 0; i < 4; i++)
                #pragma unroll
                for (int j = 0; j < 4; j++)
                    mma16(acc[i][j], a[i], b[j][0], b[j][1]);
        }
    }

    #pragma unroll
    for (int i = 0; i < 4; i++) {
        #pragma unroll
        for (int j = 0; j < 4; j++) {
            int col_g = n0 + wn * 32 + (j >> 1) * 16 + (j & 1) * 8 + 2 * tig;
            int hh = col_g >> 6, e = col_g & 63;
            float b0 = bias[col_g], b1 = bias[col_g + 1];
            int m = m0 + wm * 64 + i * 16 + gid;
            int bb = m >> 10, s = m & 1023;
            *(__half2*)&out[(((size_t)bb * NH + hh) * NS + s) * NDH + e] =
                __floats2half2_rn((acc[i][j][0] + b0) * osc, (acc[i][j][1] + b1) * osc);
            m += 8; bb = m >> 10; s = m & 1023;
            *(__half2*)&out[(((size_t)bb * NH + hh) * NS + s) * NDH + e] =
                __floats2half2_rn((acc[i][j][2] + b0) * osc, (acc[i][j][3] + b1) * osc);
        }
    }
}

// ---------------------------------------------------------------------------
// Kernel 2: fused attention (round-10 proven version, unchanged).
// ---------------------------------------------------------------------------
__global__ __launch_bounds__(256, 2) void attn_fused(float* __restrict__ probs)
{
    extern __shared__ __half smh[];
    __half* Qs = smh;                  // 64 x 72
    __half* Kb = Qs + 64 * 72;         // 2 x 64 x 72
    __half* Vb = Kb + 2 * 64 * 72;     // 2 x 64 x 72
    float* red  = (float*)(Vb + 2 * 64 * 72);  // 64 x 68
    float* ssum = red + 64 * 68;               // 2 x 64
    float* sinv = ssum + 128;                  // 64

    const int bh = blockIdx.y;
    const int s0 = blockIdx.x * 64;
    const __half* qg = g_q + (size_t)bh * NS * NDH;
    const __half* kg = g_k + (size_t)bh * NS * NDH;
    const __half* vg = g_v + (size_t)bh * NS * NDH;

    const int tid = threadIdx.x, lane = tid & 31, warp = tid >> 5;
    const int gid = lane >> 2, tig = lane & 3;
    const int wm = warp >> 1, wn = warp & 1;   // 4 x 2

    const unsigned Q_sh = (unsigned)__cvta_generic_to_shared(Qs);
    const unsigned K_sh = (unsigned)__cvta_generic_to_shared(Kb);
    const unsigned V_sh = (unsigned)__cvta_generic_to_shared(Vb);
    const int aoff = a_off(lane, 72), boff = b_off(lane, 72);

    auto issue_k = [&](int kt) {
        __half* K = Kb + (kt & 1) * 64 * 72;
        const __half* src = kg + (size_t)kt * 64 * NDH;
        #pragma unroll
        for (int p = 0; p < 2; p++) {
            int i = tid + p * 256;
            int row = i >> 3, c8 = (i & 7) * 8;
            cp16(&K[row * 72 + c8], &src[row * 64 + c8]);
        }
    };
    auto issue_v = [&](int kt) {
        __half* V = Vb + (kt & 1) * 64 * 72;
        const __half* src = vg + (size_t)kt * 64 * NDH;
        #pragma unroll
        for (int p = 0; p < 2; p++) {
            int i = tid + p * 256;
            int row = i >> 3, c8 = (i & 7) * 8;
            cp16(&V[row * 72 + c8], &src[row * 64 + c8]);
        }
    };

    #pragma unroll
    for (int p = 0; p < 2; p++) {
        int i = tid + p * 256;
        int row = i >> 3, c8 = (i & 7) * 8;
        cp16(&Qs[row * 72 + c8], &qg[(size_t)(s0 + row) * 64 + c8]);
    }
    issue_k(0); issue_v(0);
    cp_commit();

    unsigned aq[4][4];
    float ccv[8][4] = {};
    float srow[2] = {};

    for (int kt = 0; kt < 16; kt++) {
        cp_wait0();
        __syncthreads();
        if (kt + 1 < 16) { issue_k(kt + 1); issue_v(kt + 1); cp_commit(); }

        if (kt == 0) {
            #pragma unroll
            for (int e = 0; e < 4; e++)
                ldsm4(aq[e], Q_sh + ((wm * 16) * 72 + e * 16 + aoff) * 2);
        }

        const unsigned Kbuf = K_sh + (kt & 1) * 64 * 72 * 2;
        const unsigned Vbuf = V_sh + (kt & 1) * 64 * 72 * 2;

        float cc[4][4] = {};
        #pragma unroll
        for (int e = 0; e < 4; e++) {
            #pragma unroll
            for (int nt = 0; nt < 2; nt++) {
                unsigned t[4];
                ldsm4(t, Kbuf + ((wn * 32 + nt * 16) * 72 + e * 16 + boff) * 2);
                mma16(cc[nt * 2 + 0], aq[e], t[0], t[1]);
                mma16(cc[nt * 2 + 1], aq[e], t[2], t[3]);
            }
        }

        unsigned pa[2][4];
        #pragma unroll
        for (int ks = 0; ks < 2; ks++) {
            pa[ks][0] = ex2h2(pack_h2(cc[ks * 2][0],     cc[ks * 2][1]));
            pa[ks][1] = ex2h2(pack_h2(cc[ks * 2][2],     cc[ks * 2][3]));
            pa[ks][2] = ex2h2(pack_h2(cc[ks * 2 + 1][0], cc[ks * 2 + 1][1]));
            pa[ks][3] = ex2h2(pack_h2(cc[ks * 2 + 1][2], cc[ks * 2 + 1][3]));
        }
        {
            unsigned slo = hadd2(hadd2(pa[0][0], pa[0][2]), hadd2(pa[1][0], pa[1][2]));
            unsigned shi = hadd2(hadd2(pa[0][1], pa[0][3]), hadd2(pa[1][1], pa[1][3]));
            float2 f0 = h2_to_f2(slo); srow[0] += f0.x + f0.y;
            float2 f1 = h2_to_f2(shi); srow[1] += f1.x + f1.y;
        }

        #pragma unroll
        for (int ks = 0; ks < 2; ks++) {
            #pragma unroll
            for (int e0 = 0; e0 < 4; e0++) {
                unsigned bt[4];
                ldsm4t(bt, Vbuf + ((wn * 32 + ks * 16) * 72 + e0 * 16 + aoff) * 2);
                mma16(ccv[e0 * 2 + 0], pa[ks], bt[0], bt[1]);
                mma16(ccv[e0 * 2 + 1], pa[ks], bt[2], bt[3]);
            }
        }
    }

    srow[0] += __shfl_xor_sync(0xFFFFFFFFu, srow[0], 1);
    srow[0] += __shfl_xor_sync(0xFFFFFFFFu, srow[0], 2);
    srow[1] += __shfl_xor_sync(0xFFFFFFFFu, srow[1], 1);
    srow[1] += __shfl_xor_sync(0xFFFFFFFFu, srow[1], 2);
    if (tig == 0) {
        ssum[wn * 64 + wm * 16 + gid]     = srow[0];
        ssum[wn * 64 + wm * 16 + gid + 8] = srow[1];
    }
    if (wn == 1) {
        #pragma unroll
        for (int f = 0; f < 8; f++) {
            int col = f * 8 + 2 * tig;
            *(float2*)&red[(wm * 16 + gid) * 68 + col]     = *(float2*)&ccv[f][0];
            *(float2*)&red[(wm * 16 + gid + 8) * 68 + col] = *(float2*)&ccv[f][2];
        }
    }
    issue_k(0); cp_commit();
    __syncthreads();
    if (tid < 64)
        sinv[tid] = 1.0f / (ssum[tid] + ssum[64 + tid]);
    __syncthreads();

    if (wn == 0) {
        const int b = bh / NH, h = bh % NH;
        const float ilo = sinv[wm * 16 + gid];
        const float ihi = sinv[wm * 16 + gid + 8];
        #pragma unroll
        for (int f = 0; f < 8; f++) {
            int col = f * 8 + 2 * tig;
            float2 r0 = *(float2*)&red[(wm * 16 + gid) * 68 + col];
            float2 r1 = *(float2*)&red[(wm * 16 + gid + 8) * 68 + col];
            int sr = s0 + wm * 16 + gid;
            *(__half2*)&g_ctx[((size_t)b * NS + sr) * ND + h * NDH + col] =
                __floats2half2_rn((ccv[f][0] + r0.x) * ilo, (ccv[f][1] + r0.y) * ilo);
            *(__half2*)&g_ctx[((size_t)b * NS + sr + 8) * ND + h * NDH + col] =
                __floats2half2_rn((ccv[f][2] + r1.x) * ihi, (ccv[f][3] + r1.y) * ihi);
        }
    }

    const float inv_lo = sinv[wm * 16 + gid];
    const float inv_hi = sinv[wm * 16 + gid + 8];
    float* prow_lo = probs + ((size_t)bh * NS + s0 + wm * 16 + gid) * NS;
    float* prow_hi = prow_lo + (size_t)8 * NS;

    for (int kt = 0; kt < 16; kt++) {
        cp_wait0();
        __syncthreads();
        if (kt + 1 < 16) { issue_k(kt + 1); cp_commit(); }

        const unsigned Kbuf = K_sh + (kt & 1) * 64 * 72 * 2;
        float cc[4][4] = {};
        #pragma unroll
        for (int e = 0; e < 4; e++) {
            #pragma unroll
            for (int nt = 0; nt < 2; nt++) {
                unsigned t[4];
                ldsm4(t, Kbuf + ((wn * 32 + nt * 16) * 72 + e * 16 + boff) * 2);
                mma16(cc[nt * 2 + 0], aq[e], t[0], t[1]);
                mma16(cc[nt * 2 + 1], aq[e], t[2], t[3]);
            }
        }

        #pragma unroll
        for (int jj = 0; jj < 4; jj++) {
            const int col = kt * 64 + wn * 32 + (jj >> 1) * 16 + (jj & 1) * 8 + 2 * tig;
            float2 w0, w1;
            w0.x = ex2f(cc[jj][0]) * inv_lo;
            w0.y = ex2f(cc[jj][1]) * inv_lo;
            w1.x = ex2f(cc[jj][2]) * inv_hi;
            w1.y = ex2f(cc[jj][3]) * inv_hi;
            *(float2*)&prow_lo[col] = w0;
            *(float2*)&prow_hi[col] = w1;
        }
    }
}

// ---------------------------------------------------------------------------
// Kernel 3: out = ctx @ Wo^T + bo, fp16 mma, fp32 out (round-10 proven:
// 128x128 CTA tile, warps 2x4, warp tile 64x32).
// ---------------------------------------------------------------------------
__global__ __launch_bounds__(256, 2) void oproj_mma(
    const float* __restrict__ bo, float* __restrict__ out)
{
    extern __shared__ __half smh[];
    __half* As = smh;
    __half* Bs = smh + 2 * 128 * 72;

    const int tid = threadIdx.x, lane = tid & 31, warp = tid >> 5;
    const int gid = lane >> 2, tig = lane & 3;
    const int wm = warp >> 2, wn = warp & 3;
    const int m0 = blockIdx.x * 128, n0 = blockIdx.y * 128;

    const unsigned As_sh = (unsigned)__cvta_generic_to_shared(As);
    const unsigned Bs_sh = (unsigned)__cvta_generic_to_shared(Bs);
    const int aoff = a_off(lane, 72), boff = b_off(lane, 72);

    auto issue = [&](int c) {
        __half* A = As + (c & 1) * 128 * 72;
        __half* B = Bs + (c & 1) * 128 * 72;
        const int k0 = c * 64;
        #pragma unroll
        for (int p = 0; p < 4; p++) {
            int i = tid + p * 256;
            int row = i >> 3, c8 = (i & 7) * 8;
            cp16(&A[row * 72 + c8], &g_ctx[(size_t)(m0 + row) * ND + k0 + c8]);
        }
        #pragma unroll
        for (int p = 0; p < 4; p++) {
            int i = tid + p * 256;
            int row = i >> 3, c8 = (i & 7) * 8;
            cp16(&B[row * 72 + c8], &g_wo_h[(size_t)(n0 + row) * ND + k0 + c8]);
        }
        cp_commit();
    };

    float acc[4][4][4] = {};

    issue(0);
    for (int c = 0; c < 12; c++) {
        cp_wait0();
        __syncthreads();
        if (c + 1 < 12) issue(c + 1);

        const unsigned Ab = As_sh + (c & 1) * 128 * 72 * 2;
        const unsigned Bb = Bs_sh + (c & 1) * 128 * 72 * 2;

        #pragma unroll
        for (int ks = 0; ks < 4; ks++) {
            const int Kb = ks * 16;
            unsigned a[4][4], b[4][2];
            #pragma unroll
            for (int i = 0; i < 4; i++)
                ldsm4(a[i], Ab + ((wm * 64 + i * 16) * 72 + Kb + aoff) * 2);
            #pragma unroll
            for (int jj = 0; jj < 2; jj++) {
                unsigned t[4];
                ldsm4(t, Bb + ((wn * 32 + jj * 16) * 72 + Kb + boff) * 2);
                b[jj * 2][0] = t[0]; b[jj * 2][1] = t[1];
                b[jj * 2 + 1][0] = t[2]; b[jj * 2 + 1][1] = t[3];
            }
            #pragma unroll
            for (int i = 0; i < 4; i++)
                #pragma unroll
                for (int j = 0; j < 4; j++)
                    mma16(acc[i][j], a[i], b[j][0], b[j][1]);
        }
    }

    #pragma unroll
    for (int i = 0; i < 4; i++) {
        #pragma unroll
        for (int j = 0; j < 4; j++) {
            int col = n0 + wn * 32 + (j >> 1) * 16 + (j & 1) * 8 + 2 * tig;
            float b0 = bo[col], b1 = bo[col + 1];
            int m = m0 + wm * 64 + i * 16 + gid;
            float2 v;
            v.x = acc[i][j][0] + b0; v.y = acc[i][j][1] + b1;
            *(float2*)&out[(size_t)m * ND + col] = v;
            v.x = acc[i][j][2] + b0; v.y = acc[i][j][3] + b1;
            *(float2*)&out[(size_t)(m + 8) * ND + col] = v;
        }
    }
}

// ---------------------------------------------------------------------------
extern "C" void kernel_launch(void* const* d_in, const int* in_sizes, int n_in,
                              void* d_out, int out_size)
{
    const float* x  = (const float*)d_in[0];
    const float* Wq = (const float*)d_in[1];
    const float* bq = (const float*)d_in[2];
    const float* Wk = (const float*)d_in[3];
    const float* bk = (const float*)d_in[4];
    const float* Wv = (const float*)d_in[5];
    const float* bv = (const float*)d_in[6];
    const float* Wo = (const float*)d_in[7];
    const float* bo = (const float*)d_in[8];

    float* out = (float*)d_out;

    const size_t BSD  = (size_t)NB * NS * ND;
    const size_t BHSS = (size_t)NB * NH * NS * NS;

    float* probs;
    if ((size_t)out_size >= BSD + BHSS) {
        probs = out + BSD;
    } else {
        cudaGetSymbolAddress((void**)&probs, g_probs_fb);
    }

    const int gemm_smem = 2 * 128 * 72 * 2 * 2;                        // 73,728 B
    const int attn_smem = (64 * 72 * 5) * 2 + (64 * 68 + 128 + 64) * 4; // 64,256 B
    cudaFuncSetAttribute(qkv_mma,    cudaFuncAttributeMaxDynamicSharedMemorySize, gemm_smem);
    cudaFuncSetAttribute(attn_fused, cudaFuncAttributeMaxDynamicSharedMemorySize, attn_smem);
    cudaFuncSetAttribute(oproj_mma,  cudaFuncAttributeMaxDynamicSharedMemorySize, gemm_smem);

    prep_all   <<<PREP_CVT_BLOCKS + PREP_WT_BLOCKS, 256>>>(x, Wo, Wq, Wk, Wv);
    qkv_mma    <<<dim3(64, 6, 3), 256, gemm_smem>>>(bq, bk, bv);
    attn_fused <<<dim3(16, 96), 256, attn_smem>>>(probs);
    oproj_mma  <<<dim3(64, 6), 256, gemm_smem>>>(bo, out);
}